// round 3
// baseline (speedup 1.0000x reference)
#include <cuda_runtime.h>

// InteractionArch: out[b] = concat(dense[b] (128), sparse[b]·dense[b] (26),
//                                  triu_{k=1}(sparse[b]·sparse[b]^T) (325))
// B=16384, F=26, D=128, out stride 479 fp32 (row base only 4B-aligned).

#define B_TOT 16384
#define NF 26
#define DD 128
#define NQ 32            // float4 quads per vector (128/4)
#define NV 28            // 26 sparse + 1 dense (slot 26) + 1 zero pad (slot 27)
#define OUT_STRIDE 479
#define BPB 3            // batch rows per block (1 warp each)

__global__ void __launch_bounds__(BPB * 32) interact_kernel(
    const float* __restrict__ dense,
    const float* __restrict__ sparse,
    float* __restrict__ out)
{
    __shared__ float Xs[BPB][NV][DD];

    const int warp = threadIdx.x >> 5;
    const int lane = threadIdx.x & 31;
    const int b    = blockIdx.x * BPB + warp;
    if (b >= B_TOT) return;

    float*        xb  = &Xs[warp][0][0];
    float4*       xb4 = reinterpret_cast<float4*>(xb);
    const float4* sp4 = reinterpret_cast<const float4*>(sparse + (size_t)b * NF * DD);

    // ---- Load phase: coalesced float4 loads, conflict-free row-major smem stores ----
    #pragma unroll
    for (int f = 0; f < NF; f++) {
        xb4[f * 32 + lane] = sp4[f * 32 + lane];
    }
    // dense -> smem slot 26, and pass through to output[0:128] (scalar stores: row
    // base not 16B-aligned).
    float4 dv = reinterpret_cast<const float4*>(dense + (size_t)b * DD)[lane];
    xb4[26 * 32 + lane] = dv;
    {
        float* ob = out + (size_t)b * OUT_STRIDE;
        ob[4 * lane + 0] = dv.x;
        ob[4 * lane + 1] = dv.y;
        ob[4 * lane + 2] = dv.z;
        ob[4 * lane + 3] = dv.w;
    }
    // zero pad slot 27
    xb4[27 * 32 + lane] = make_float4(0.f, 0.f, 0.f, 0.f);

    __syncwarp();

    if (lane >= 28) return;   // 28 upper-tri 4x4 tiles of the 7x7 tile grid

    // ---- Tile mapping: lane -> (ti, tj), ti<=tj, row lengths 7,6,5,4,3,2,1 ----
    int ti = 0, rem = lane;
    while (rem >= 7 - ti) { rem -= 7 - ti; ti++; }
    const int tj = ti + rem;
    const int i0 = 4 * ti;
    const int j0 = 4 * tj;

    const float4* __restrict__ pi4 = reinterpret_cast<const float4*>(xb + i0 * DD);
    const float4* __restrict__ pj4 = reinterpret_cast<const float4*>(xb + j0 * DD);

    float acc[4][4];
    #pragma unroll
    for (int ii = 0; ii < 4; ii++)
        #pragma unroll
        for (int jj = 0; jj < 4; jj++)
            acc[ii][jj] = 0.f;

    // ---- Compute: per-lane quad rotation -> conflict-free LDS.128 ----
    // Lane l at quad-step kk reads quad (kk+l)&31 -> bank-quad ((kk+l)&31)%8,
    // distinct within each 8-lane phase group => no conflicts.
    #pragma unroll 4
    for (int kk = 0; kk < NQ; kk++) {
        const int kq = (kk + lane) & (NQ - 1);
        float4 xi[4], xj[4];
        #pragma unroll
        for (int ii = 0; ii < 4; ii++) xi[ii] = pi4[ii * NQ + kq];
        #pragma unroll
        for (int jj = 0; jj < 4; jj++) xj[jj] = pj4[jj * NQ + kq];
        #pragma unroll
        for (int ii = 0; ii < 4; ii++)
            #pragma unroll
            for (int jj = 0; jj < 4; jj++) {
                acc[ii][jj] = fmaf(xi[ii].x, xj[jj].x, acc[ii][jj]);
                acc[ii][jj] = fmaf(xi[ii].y, xj[jj].y, acc[ii][jj]);
                acc[ii][jj] = fmaf(xi[ii].z, xj[jj].z, acc[ii][jj]);
                acc[ii][jj] = fmaf(xi[ii].w, xj[jj].w, acc[ii][jj]);
            }
    }

    // ---- Epilogue: scatter the needed dots (scalar stores) ----
    float* ob = out + (size_t)b * OUT_STRIDE;
    #pragma unroll
    for (int ii = 0; ii < 4; ii++) {
        #pragma unroll
        for (int jj = 0; jj < 4; jj++) {
            const int i = i0 + ii;
            const int j = j0 + jj;
            if (i < j && j <= 26) {
                int dst;
                if (j == 26) {
                    dst = 128 + i;                                   // sparse·dense
                } else {
                    dst = 154 + i * 25 - (i * (i - 1)) / 2 + (j - i - 1); // pair
                }
                ob[dst] = acc[ii][jj];
            }
        }
    }
}

extern "C" void kernel_launch(void* const* d_in, const int* in_sizes, int n_in,
                              void* d_out, int out_size)
{
    (void)n_in; (void)out_size;
    const float* a = (const float*)d_in[0];
    const float* b = (const float*)d_in[1];
    // dense has B*D = 2,097,152 elems; sparse has B*F*D = 54,525,952 elems.
    const float* dense  = (in_sizes[0] < in_sizes[1]) ? a : b;
    const float* sparse = (in_sizes[0] < in_sizes[1]) ? b : a;

    const int grid = (B_TOT + BPB - 1) / BPB;
    interact_kernel<<<grid, BPB * 32>>>(dense, sparse, (float*)d_out);
}

// round 4
// speedup vs baseline: 1.0003x; 1.0003x over previous
#include <cuda_runtime.h>

// InteractionArch: out[b] = concat(dense[b] (128), sparse[b]·dense[b] (26),
//                                  triu_{k=1}(sparse[b]·sparse[b]^T) (325))
// B=16384, F=26, D=128, out stride 479 fp32 (row base only 4B-aligned).
//
// R4 design: 28-vector set (26 sparse + dense + zero pad) -> 4x4 grid of 7x7
// register tiles; 10 upper-tri tiles; 1 lane per tile; 3 batch rows per warp
// (30 active lanes). Cuts smem read bytes 1.75x vs 4x4 tiling.

#define B_TOT 16384
#define NF 26
#define DD 128
#define NQ 32            // float4 quads per vector
#define NV 28
#define OUT_STRIDE 479
#define RPW 3            // batch rows per warp (one warp per block)

__global__ void __launch_bounds__(32) interact_kernel(
    const float* __restrict__ dense,
    const float* __restrict__ sparse,
    float* __restrict__ out)
{
    __shared__ float Xs[RPW][NV][DD];   // 43008 B static

    const int lane = threadIdx.x;
    const int b0   = blockIdx.x * RPW;

    // ---- Load phase: all 32 lanes, coalesced float4 ----
    #pragma unroll
    for (int r = 0; r < RPW; r++) {
        const int b = b0 + r;
        if (b >= B_TOT) break;
        float4*       xb4 = reinterpret_cast<float4*>(&Xs[r][0][0]);
        const float4* sp4 = reinterpret_cast<const float4*>(sparse + (size_t)b * NF * DD);
        #pragma unroll
        for (int f = 0; f < NF; f++) {
            xb4[f * 32 + lane] = sp4[f * 32 + lane];
        }
        float4 dv = reinterpret_cast<const float4*>(dense + (size_t)b * DD)[lane];
        xb4[26 * 32 + lane] = dv;
        xb4[27 * 32 + lane] = make_float4(0.f, 0.f, 0.f, 0.f);
        // dense passthrough to out[0:128] (scalar: row base only 4B-aligned)
        float* ob = out + (size_t)b * OUT_STRIDE;
        ob[4 * lane + 0] = dv.x;
        ob[4 * lane + 1] = dv.y;
        ob[4 * lane + 2] = dv.z;
        ob[4 * lane + 3] = dv.w;
    }
    __syncwarp();

    // ---- Lane -> (row, tile) mapping: 3 rows x 10 tiles ----
    const int r = lane / 10;            // 0..2 (lane 30,31 idle)
    const int t = lane - r * 10;        // 0..9
    const int b = b0 + r;
    if (lane >= 30 || b >= B_TOT) return;

    // 10 upper-tri tiles of the 4x4 tile grid (row lengths 4,3,2,1)
    const int ti = (t < 4) ? 0 : (t < 7) ? 1 : (t < 9) ? 2 : 3;
    const int tj = (t < 4) ? t : (t < 7) ? t - 3 : (t < 9) ? t - 5 : 3;
    const bool diag = (ti == tj);

    const float4* __restrict__ pi4 = reinterpret_cast<const float4*>(&Xs[r][7 * ti][0]);
    const float4* __restrict__ pj4 = reinterpret_cast<const float4*>(&Xs[r][7 * tj][0]);

    float acc[7][7];
    #pragma unroll
    for (int ii = 0; ii < 7; ii++)
        #pragma unroll
        for (int jj = 0; jj < 7; jj++)
            acc[ii][jj] = 0.f;

    // ---- Compute: per-lane quad rotation -> conflict-free LDS.128 ----
    #pragma unroll 1
    for (int kk = 0; kk < NQ; kk++) {
        const int kq = (kk + lane) & (NQ - 1);
        float4 xi[7], xj[7];
        #pragma unroll
        for (int ii = 0; ii < 7; ii++) xi[ii] = pi4[ii * NQ + kq];
        #pragma unroll
        for (int jj = 0; jj < 7; jj++) xj[jj] = diag ? xi[jj] : pj4[jj * NQ + kq];
        #pragma unroll
        for (int ii = 0; ii < 7; ii++)
            #pragma unroll
            for (int jj = 0; jj < 7; jj++) {
                float s = acc[ii][jj];
                s = fmaf(xi[ii].x, xj[jj].x, s);
                s = fmaf(xi[ii].y, xj[jj].y, s);
                s = fmaf(xi[ii].z, xj[jj].z, s);
                s = fmaf(xi[ii].w, xj[jj].w, s);
                acc[ii][jj] = s;
            }
    }

    // ---- Epilogue: scatter needed dots (i<j, j<=26) ----
    float* ob = out + (size_t)b * OUT_STRIDE;
    #pragma unroll
    for (int ii = 0; ii < 7; ii++) {
        #pragma unroll
        for (int jj = 0; jj < 7; jj++) {
            const int i = 7 * ti + ii;
            const int j = 7 * tj + jj;
            if (i < j && j <= 26) {
                int dst;
                if (j == 26) {
                    dst = 128 + i;                                       // sparse·dense
                } else {
                    dst = 154 + i * 25 - (i * (i - 1)) / 2 + (j - i - 1); // pair
                }
                ob[dst] = acc[ii][jj];
            }
        }
    }
}

extern "C" void kernel_launch(void* const* d_in, const int* in_sizes, int n_in,
                              void* d_out, int out_size)
{
    (void)n_in; (void)out_size;
    const float* a = (const float*)d_in[0];
    const float* b = (const float*)d_in[1];
    // dense has B*D = 2,097,152 elems; sparse has B*F*D = 54,525,952 elems.
    const float* dense  = (in_sizes[0] < in_sizes[1]) ? a : b;
    const float* sparse = (in_sizes[0] < in_sizes[1]) ? b : a;

    const int grid = (B_TOT + RPW - 1) / RPW;
    interact_kernel<<<grid, 32>>>(dense, sparse, (float*)d_out);
}

// round 5
// speedup vs baseline: 1.3063x; 1.3058x over previous
#include <cuda_runtime.h>

// InteractionArch: out[b] = concat(dense[b] (128), sparse[b]·dense[b] (26),
//                                  triu_{k=1}(sparse[b]·sparse[b]^T) (325))
// B=16384, F=26, D=128, out stride 479 fp32 (row base only 4B-aligned).
//
// R5: k-chunked (4 x 32 floats), double-buffered cp.async pipeline.
// 7x7 register tiles over the 28-vector set (4x4 tile grid, 10 upper-tri
// tiles), 1 lane/tile, 3 batch rows per warp (30 active compute lanes).
// smem/block 21KB -> 10 single-warp blocks/SM = 30 rows in flight.

#define B_TOT 16384
#define NF 26
#define DD 128
#define NV 28
#define CHUNK 32          // floats per k-chunk
#define CQ 8              // quads per chunk
#define NCH 4             // chunks (128/32)
#define OUT_STRIDE 479
#define RPW 3             // batch rows per warp

__device__ __forceinline__ void cp_async16(void* smem, const void* gmem) {
    unsigned s = (unsigned)__cvta_generic_to_shared(smem);
    asm volatile("cp.async.cg.shared.global [%0], [%1], 16;" :: "r"(s), "l"(gmem));
}
__device__ __forceinline__ void cp_commit() {
    asm volatile("cp.async.commit_group;");
}
template <int N>
__device__ __forceinline__ void cp_wait() {
    asm volatile("cp.async.wait_group %0;" :: "n"(N));
}

__global__ void __launch_bounds__(32, 10) interact_kernel(
    const float* __restrict__ dense,
    const float* __restrict__ sparse,
    float* __restrict__ out)
{
    __shared__ float Xs[RPW][2][NV][CHUNK];   // 21504 B

    const int lane = threadIdx.x;
    const int b0   = blockIdx.x * RPW;

    // ---- zero pad slot 27 (both buffers, never overwritten) ----
    #pragma unroll
    for (int t = 0; t < 6; t++) {
        int idx = lane + 32 * t;           // RPW*2*CHUNK = 192 floats
        int rr  = idx / (2 * CHUNK);
        int rem = idx - rr * 2 * CHUNK;
        Xs[rr][rem / CHUNK][27][rem % CHUNK] = 0.f;
    }

    // ---- dense passthrough to out[0:128] (scalar stores) ----
    #pragma unroll
    for (int r = 0; r < RPW; r++) {
        const int b = b0 + r;
        if (b >= B_TOT) break;
        float4 dv = reinterpret_cast<const float4*>(dense + (size_t)b * DD)[lane];
        float* ob = out + (size_t)b * OUT_STRIDE;
        ob[4 * lane + 0] = dv.x;
        ob[4 * lane + 1] = dv.y;
        ob[4 * lane + 2] = dv.z;
        ob[4 * lane + 3] = dv.w;
    }

    // ---- chunk loader (warp-cooperative) ----
    auto load_chunk = [&](int c, int buf) {
        // sparse: 26 vec * 8 quads * 3 rows = 624 transfers
        #pragma unroll
        for (int t = 0; t < 20; t++) {
            int idx = lane + 32 * t;
            if (idx < NF * CQ * RPW) {
                int r   = idx / (NF * CQ);
                int rem = idx - r * NF * CQ;
                int v   = rem >> 3;
                int q   = rem & 7;
                int b   = b0 + r;
                if (b < B_TOT) {
                    const float* g = sparse + (size_t)b * NF * DD + v * DD + c * CHUNK + q * 4;
                    cp_async16(&Xs[r][buf][v][q * 4], g);
                }
            }
        }
        // dense slot 26: 8 quads * 3 rows = 24
        if (lane < CQ * RPW) {
            int r = lane >> 3, q = lane & 7;
            int b = b0 + r;
            if (b < B_TOT)
                cp_async16(&Xs[r][buf][26][q * 4],
                           dense + (size_t)b * DD + c * CHUNK + q * 4);
        }
        cp_commit();
    };

    // ---- lane -> (row, tile) mapping for compute ----
    const int r  = lane / 10;                 // 0..2 (lanes 30,31 idle in compute)
    const int t  = lane - r * 10;             // 0..9
    const int bc = b0 + r;
    const bool active = (lane < 30) && (bc < B_TOT);

    const int ti = (t < 4) ? 0 : (t < 7) ? 1 : (t < 9) ? 2 : 3;
    const int tj = (t < 4) ? t : (t < 7) ? t - 3 : (t < 9) ? t - 5 : 3;

    float acc[7][7];
    #pragma unroll
    for (int ii = 0; ii < 7; ii++)
        #pragma unroll
        for (int jj = 0; jj < 7; jj++)
            acc[ii][jj] = 0.f;

    // ---- pipelined chunk loop ----
    load_chunk(0, 0);
    #pragma unroll
    for (int c = 0; c < NCH; c++) {
        const int buf = c & 1;
        if (c + 1 < NCH) { load_chunk(c + 1, buf ^ 1); cp_wait<1>(); }
        else             { cp_wait<0>(); }
        __syncwarp();

        if (active) {
            const float4* __restrict__ pi4 =
                reinterpret_cast<const float4*>(&Xs[r][buf][7 * ti][0]);
            const float4* __restrict__ pj4 =
                reinterpret_cast<const float4*>(&Xs[r][buf][7 * tj][0]);
            #pragma unroll 1
            for (int kk = 0; kk < CQ; kk++) {
                const int kq = (kk + lane) & (CQ - 1);
                float4 xi[7], xj[7];
                #pragma unroll
                for (int ii = 0; ii < 7; ii++) xi[ii] = pi4[ii * CQ + kq];
                #pragma unroll
                for (int jj = 0; jj < 7; jj++) xj[jj] = pj4[jj * CQ + kq];
                #pragma unroll
                for (int ii = 0; ii < 7; ii++)
                    #pragma unroll
                    for (int jj = 0; jj < 7; jj++) {
                        float s = acc[ii][jj];
                        s = fmaf(xi[ii].x, xj[jj].x, s);
                        s = fmaf(xi[ii].y, xj[jj].y, s);
                        s = fmaf(xi[ii].z, xj[jj].z, s);
                        s = fmaf(xi[ii].w, xj[jj].w, s);
                        acc[ii][jj] = s;
                    }
            }
        }
        __syncwarp();   // all lanes done reading buf before it is refilled
    }

    // ---- epilogue: scatter needed dots (i<j, j<=26) ----
    if (!active) return;
    float* ob = out + (size_t)bc * OUT_STRIDE;
    #pragma unroll
    for (int ii = 0; ii < 7; ii++) {
        #pragma unroll
        for (int jj = 0; jj < 7; jj++) {
            const int i = 7 * ti + ii;
            const int j = 7 * tj + jj;
            if (i < j && j <= 26) {
                int dst;
                if (j == 26) {
                    dst = 128 + i;                                        // sparse·dense
                } else {
                    dst = 154 + i * 25 - (i * (i - 1)) / 2 + (j - i - 1); // pair
                }
                ob[dst] = acc[ii][jj];
            }
        }
    }
}

extern "C" void kernel_launch(void* const* d_in, const int* in_sizes, int n_in,
                              void* d_out, int out_size)
{
    (void)n_in; (void)out_size;
    const float* a = (const float*)d_in[0];
    const float* b = (const float*)d_in[1];
    // dense has B*D = 2,097,152 elems; sparse has B*F*D = 54,525,952 elems.
    const float* dense  = (in_sizes[0] < in_sizes[1]) ? a : b;
    const float* sparse = (in_sizes[0] < in_sizes[1]) ? b : a;

    const int grid = (B_TOT + RPW - 1) / RPW;
    interact_kernel<<<grid, 32>>>(dense, sparse, (float*)d_out);
}